// round 12
// baseline (speedup 1.0000x reference)
#include <cuda_runtime.h>
#include <cuda_bf16.h>
#include <cstdint>

// Embedding gather: out[token, :] = W[:, ids[token]], W row-major [D_MODEL, VOCAB].
// R12: clean 512B-request retest. Rows are loaded as LDG.128 from the
// aligned-down base (VOCAB odd -> per-row shift = row&3 since c0 % 4 == 0)
// and stored RAW into a 132-word smem row (STS.128, conflict-free); the 16B
// tail goes inline at words 128..131. Distribute is R10's loop plus ONE add:
//   v = sstage[lane*132 + col + (lane&3)]
// No conditionals, no side buffers (R11's mistake).

#define VOCAB     50257
#define D_MODEL   1024
#define N_TOK     (4 * 4096)
#define W_SIZE    ((long)D_MODEL * VOCAB)

#define TILE_C    128
#define TILE_BITS 7
#define N_TILES   ((VOCAB + TILE_C - 1) / TILE_C)   // 393
#define TILE_D    32
#define N_CHUNK   (D_MODEL / TILE_D)                // 32
#define PAD       132                               // mult of 4: STS.128-aligned rows
#define STAGE_ELEMS (TILE_D * PAD)                  // 4224 floats = 16.9 KB
#define CAP       1024
#define NTHREADS  512

__global__ __launch_bounds__(NTHREADS, 3)
void gather_tile_kernel(const int* __restrict__ ids,
                        const float* __restrict__ W,
                        float* __restrict__ out) {
    const int tile = blockIdx.x;

    __shared__ float buf[2][STAGE_ELEMS];       // 33.8 KB
    __shared__ int   s_list[CAP];               // 4 KB
    __shared__ int   s_cnt;

    const int tid  = threadIdx.x;
    const int lane = tid & 31;
    const int wid  = tid >> 5;                  // 16 warps
    const int c0   = tile * TILE_C;             // c0 % 4 == 0

    // Each warp owns rows {2*wid, 2*wid+1} of every chunk.
    const int r0 = wid * 2;
    const int r1 = r0 + 1;

    // Aligned-down element bases for chunk 0 (advance by 32*VOCAB per chunk;
    // stride is a multiple of 4, so alignment and shift are chunk-invariant).
    const long STRIDE = 32L * VOCAB;
    long a0 = (((long)r0 * VOCAB + c0) & ~3L) + 4 * lane;
    long a1 = (((long)r1 * VOCAB + c0) & ~3L) + 4 * lane;
    // Tail: lane 0 -> row r0, lane 16 -> row r1 (16B at strip words 128..131).
    const int  trow = r0 + (lane >> 4);
    long at = (((long)trow * VOCAB + c0) & ~3L) + 128;
    const bool tlane = ((lane & 15) == 0);

    if (tid == 0) s_cnt = 0;

    float4 m0c = make_float4(0, 0, 0, 0), m1c = m0c, tc = m0c;
    float4 m0n, m1n, tn;

    // Prologue: chunk-0 loads; filter runs in their shadow.
    if (a0 + 4 <= W_SIZE) m0c = *reinterpret_cast<const float4*>(W + a0);
    if (a1 + 4 <= W_SIZE) m1c = *reinterpret_cast<const float4*>(W + a1);
    if (tlane && at + 4 <= W_SIZE) tc = *reinterpret_cast<const float4*>(W + at);

    __syncthreads();   // s_cnt = 0 visible

    // Filter: find tokens whose id falls in this tile. Order irrelevant.
    const int4* __restrict__ ids4 = (const int4*)ids;
    for (int i = tid; i < N_TOK / 4; i += NTHREADS) {
        const int4 v = ids4[i];
        const int base_tok = i * 4;
        #pragma unroll
        for (int k = 0; k < 4; k++) {
            const int id = (&v.x)[k];
            if ((id >> TILE_BITS) == tile) {
                const int pos = atomicAdd(&s_cnt, 1);
                if (pos < CAP)
                    s_list[pos] = ((id & (TILE_C - 1)) << 16) | (base_tok + k);
            }
        }
    }
    __syncthreads();

    const int cnt = s_cnt;
    if (cnt == 0) return;                      // uniform block exit
    const bool overflow = (cnt > CAP);
    const int n = overflow ? 0 : cnt;
    const int shift_l = lane & 3;              // distribute-row shift

    for (int c = 0; c < N_CHUNK; c++) {
        // Issue chunk c+1 loads early (consumed next iteration).
        if (c + 1 < N_CHUNK) {
            const long b0 = a0 + STRIDE, b1 = a1 + STRIDE, bt = at + STRIDE;
            m0n = make_float4(0, 0, 0, 0); m1n = m0n; tn = m0n;
            if (b0 + 4 <= W_SIZE) m0n = *reinterpret_cast<const float4*>(W + b0);
            if (b1 + 4 <= W_SIZE) m1n = *reinterpret_cast<const float4*>(W + b1);
            if (tlane && bt + 4 <= W_SIZE) tn = *reinterpret_cast<const float4*>(W + bt);
            a0 = b0; a1 = b1; at = bt;
        }

        // Stage chunk c: raw strips, STS.128 conflict-free (contiguous rows).
        // buf[c&1] last distributed at iter c-2, separated by barrier c-1.
        float* sstage = &buf[c & 1][0];
        *reinterpret_cast<float4*>(&sstage[r0 * PAD + 4 * lane]) = m0c;
        *reinterpret_cast<float4*>(&sstage[r1 * PAD + 4 * lane]) = m1c;
        if (tlane)
            *reinterpret_cast<float4*>(&sstage[trow * PAD + 128]) = tc;
        __syncthreads();

        // Distribute chunk c: strip word = col + (lane&3); one coalesced
        // 128B store per token. (4-way LDS bank conflict: stride 132.)
        const int d0 = c * TILE_D;
        for (int s = wid; s < n; s += 16) {
            const int pk    = s_list[s];
            const int col   = pk >> 16;
            const int token = pk & 0xFFFF;
            out[(long)token * D_MODEL + d0 + lane] =
                sstage[lane * PAD + col + shift_l];
        }
        if (overflow) {
            // Correct-for-any-input fallback (never taken here; idempotent).
            for (int s = wid; s < N_TOK; s += 16) {
                const int id = __ldg(&ids[s]);
                if ((id >> TILE_BITS) == tile)
                    out[(long)s * D_MODEL + d0 + lane] =
                        sstage[lane * PAD + (id & (TILE_C - 1)) + shift_l];
            }
        }

        m0c = m0n; m1c = m1n; tc = tn;
    }
}

extern "C" void kernel_launch(void* const* d_in, const int* in_sizes, int n_in,
                              void* d_out, int out_size) {
    const int* ids = nullptr;
    const float* W = nullptr;
    for (int i = 0; i < n_in; i++) {
        if (in_sizes[i] == N_TOK) ids = (const int*)d_in[i];
        else if (in_sizes[i] == D_MODEL * VOCAB) W = (const float*)d_in[i];
    }
    float* out = (float*)d_out;

    gather_tile_kernel<<<N_TILES, NTHREADS>>>(ids, W, out);
}

// round 13
// speedup vs baseline: 1.1875x; 1.1875x over previous
#include <cuda_runtime.h>
#include <cuda_bf16.h>
#include <cstdint>

// Embedding gather: out[token, :] = W[:, ids[token]], W row-major [D_MODEL, VOCAB].
// R13: warp-specialized producer/consumer. R7-R12 showed DRAM pinned ~66%
// because loads are only outstanding ~20% of each barrier-paced iteration.
// Producers (warps 0-7) stream LDG+STS through a 2-stage mbarrier ring with
// no block-wide barriers; consumers (warps 8-15) filter ids and distribute.

#define VOCAB     50257
#define D_MODEL   1024
#define N_TOK     (4 * 4096)

#define TILE_C    128
#define TILE_BITS 7
#define N_TILES   ((VOCAB + TILE_C - 1) / TILE_C)   // 393
#define TILE_D    32
#define N_CHUNK   (D_MODEL / TILE_D)                // 32
#define NSTAGE    2
#define PAD       (TILE_C + 1)                      // 129: conflict-free
#define STAGE_ELEMS (TILE_D * PAD)                  // 4128 floats
#define CAP       1024
#define NTHREADS  512

#define MBAR_INIT(addr, count) \
    asm volatile("mbarrier.init.shared.b64 [%0], %1;" :: "r"(addr), "r"(count) : "memory")
#define MBAR_ARRIVE(addr) \
    asm volatile("mbarrier.arrive.shared.b64 _, [%0];" :: "r"(addr) : "memory")
#define MBAR_WAIT(addr, parity) do {                                          \
    asm volatile(                                                             \
        "{\n\t.reg .pred P1;\n\t"                                             \
        "WAIT_LOOP_%=:\n\t"                                                   \
        "mbarrier.try_wait.parity.acquire.cta.shared::cta.b64 P1, [%0], %1, 0x989680;\n\t" \
        "@P1 bra.uni WAIT_DONE_%=;\n\t"                                       \
        "bra.uni WAIT_LOOP_%=;\n\t"                                           \
        "WAIT_DONE_%=:\n\t}"                                                  \
        :: "r"(addr), "r"(parity) : "memory");                                \
} while (0)

__global__ __launch_bounds__(NTHREADS, 3)
void gather_tile_kernel(const int* __restrict__ ids,
                        const float* __restrict__ W,
                        float* __restrict__ out) {
    const int tile = blockIdx.x;

    __shared__ float buf[NSTAGE][STAGE_ELEMS];   // 33 KB
    __shared__ int   s_list[CAP];                // 4 KB
    __shared__ int   s_cnt;
    __shared__ __align__(8) unsigned long long s_mbar[2 * NSTAGE]; // full[2], empty[2]

    const int tid  = threadIdx.x;
    const int lane = tid & 31;
    const int wid  = tid >> 5;                 // 16 warps
    const int c0   = tile * TILE_C;

    const uint32_t mb0 = (uint32_t)__cvta_generic_to_shared(&s_mbar[0]);
    #define FULL_ADDR(s)  (mb0 + (uint32_t)((s) * 8))
    #define EMPTY_ADDR(s) (mb0 + (uint32_t)((NSTAGE + (s)) * 8))

    if (tid == 0) {
        #pragma unroll
        for (int s = 0; s < NSTAGE; s++) {
            MBAR_INIT(FULL_ADDR(s), 8);    // 8 producer-warp arrivals
            MBAR_INIT(EMPTY_ADDR(s), 8);   // 8 consumer-warp arrivals
        }
        s_cnt = 0;
    }
    __syncthreads();   // mbarriers + s_cnt visible; ONLY block-wide barrier

    if (wid < 8) {
        // ---------------- PRODUCER: warp p owns rows 4p..4p+3 ----------------
        const int p4 = wid * 4;
        int gc[4];
        #pragma unroll
        for (int j = 0; j < 4; j++)
            gc[j] = min(c0 + j * 32 + lane, VOCAB - 1);  // clamp: last tile only

        float v[16];
        // Prefetch chunk 0.
        #pragma unroll
        for (int i = 0; i < 4; i++) {
            const long rb = (long)(p4 + i) * VOCAB;
            #pragma unroll
            for (int j = 0; j < 4; j++)
                v[i * 4 + j] = __ldg(W + rb + gc[j]);
        }

        for (int c = 0; c < N_CHUNK; c++) {
            const int s = c & (NSTAGE - 1);
            const int ph = 1 ^ ((c >> 1) & 1);   // producer phase (starts passing)
            MBAR_WAIT(EMPTY_ADDR(s), ph);

            float* sstage = &buf[s][0];
            #pragma unroll
            for (int i = 0; i < 4; i++)
                #pragma unroll
                for (int j = 0; j < 4; j++)
                    sstage[(p4 + i) * PAD + j * 32 + lane] = v[i * 4 + j];
            __syncwarp();
            if (lane == 0) MBAR_ARRIVE(FULL_ADDR(s));

            // Issue chunk c+1 loads immediately: outstanding through the next
            // empty-wait + STS -> near-continuous DRAM occupancy.
            if (c + 1 < N_CHUNK) {
                #pragma unroll
                for (int i = 0; i < 4; i++) {
                    const long rb = (long)((c + 1) * TILE_D + p4 + i) * VOCAB;
                    #pragma unroll
                    for (int j = 0; j < 4; j++)
                        v[i * 4 + j] = __ldg(W + rb + gc[j]);
                }
            }
        }
    } else {
        // ---------------- CONSUMER: warps 8-15 ----------------
        const int cw = wid - 8;
        const int ctid = tid - 256;            // 0..255

        // Filter (runs while producers fill stages 0/1).
        const int4* __restrict__ ids4 = (const int4*)ids;
        for (int i = ctid; i < N_TOK / 4; i += 256) {
            const int4 vv = ids4[i];
            const int base_tok = i * 4;
            #pragma unroll
            for (int k = 0; k < 4; k++) {
                const int id = (&vv.x)[k];
                if ((id >> TILE_BITS) == tile) {
                    const int pos = atomicAdd(&s_cnt, 1);
                    if (pos < CAP)
                        s_list[pos] = ((id & (TILE_C - 1)) << 16) | (base_tok + k);
                }
            }
        }
        asm volatile("bar.sync 1, 256;" ::: "memory");   // consumer-only barrier

        const int cnt = s_cnt;
        const bool overflow = (cnt > CAP);
        const int n = overflow ? 0 : cnt;

        for (int c = 0; c < N_CHUNK; c++) {
            const int s = c & (NSTAGE - 1);
            const int ph = (c >> 1) & 1;
            MBAR_WAIT(FULL_ADDR(s), ph);

            const float* sstage = &buf[s][0];
            const int d0 = c * TILE_D;
            for (int t = cw; t < n; t += 8) {
                const int pk    = s_list[t];
                const int col   = pk >> 16;
                const int token = pk & 0xFFFF;
                out[(long)token * D_MODEL + d0 + lane] = sstage[lane * PAD + col];
            }
            if (overflow) {
                // Correct-for-any-input fallback (never taken here; idempotent).
                for (int t = cw; t < N_TOK; t += 8) {
                    const int id = __ldg(&ids[t]);
                    if ((id >> TILE_BITS) == tile)
                        out[(long)t * D_MODEL + d0 + lane] =
                            sstage[lane * PAD + (id & (TILE_C - 1))];
                }
            }
            __syncwarp();
            if (lane == 0) MBAR_ARRIVE(EMPTY_ADDR(s));
        }
    }
}

extern "C" void kernel_launch(void* const* d_in, const int* in_sizes, int n_in,
                              void* d_out, int out_size) {
    const int* ids = nullptr;
    const float* W = nullptr;
    for (int i = 0; i < n_in; i++) {
        if (in_sizes[i] == N_TOK) ids = (const int*)d_in[i];
        else if (in_sizes[i] == D_MODEL * VOCAB) W = (const float*)d_in[i];
    }
    float* out = (float*)d_out;

    gather_tile_kernel<<<N_TILES, NTHREADS>>>(ids, W, out);
}

// round 14
// speedup vs baseline: 1.2800x; 1.0779x over previous
#include <cuda_runtime.h>
#include <cuda_bf16.h>
#include <cstdint>

// Embedding gather: out[token, :] = W[:, ids[token]], W row-major [D_MODEL, VOCAB].
// R14: R10 (best: 48.3us @ 65.8% DRAM) with occupancy pushed from 48 to 64
// warps/SM: __launch_bounds__(512,4) forces <=32 regs; load addressing is
// restructured to one running base pointer + compile-time immediate offsets
// (p*4*VOCAB elements) so the compiler can actually hit 32 without spills.

#define VOCAB     50257
#define D_MODEL   1024
#define N_TOK     (4 * 4096)

#define TILE_C    128
#define TILE_BITS 7
#define N_TILES   ((VOCAB + TILE_C - 1) / TILE_C)   // 393
#define TILE_D    32
#define N_CHUNK   (D_MODEL / TILE_D)                // 32
#define PAD       (TILE_C + 1)                      // 129: conflict-free
#define STAGE_ELEMS (TILE_D * PAD)                  // 4128 floats
#define CAP       1024
#define NTHREADS  512

__global__ __launch_bounds__(NTHREADS, 4)
void gather_tile_kernel(const int* __restrict__ ids,
                        const float* __restrict__ W,
                        float* __restrict__ out) {
    const int tile = blockIdx.x;

    __shared__ float buf[2][STAGE_ELEMS];   // 33 KB
    __shared__ int   s_list[CAP];           // 4 KB
    __shared__ int   s_cnt;

    const int tid  = threadIdx.x;
    const int lane = tid & 31;
    const int wid  = tid >> 5;                 // 16 warps
    const int c0   = tile * TILE_C;

    // Load mapping: lc = column 0..127, lr = row-phase 0..3. Thread loads
    // rows {p*4+lr : p=0..7} of each 32-row chunk at column gcol.
    const int lc = tid & (TILE_C - 1);
    const int lr = tid >> TILE_BITS;
    const int gcol = min(c0 + lc, VOCAB - 1);  // clamp: last tile only

    // Single running pointer; the 8 in-chunk row offsets are compile-time
    // immediates (p * 4 * VOCAB elements), so addressing needs ~1 live long.
    const float* bp = W + (long)lr * VOCAB + gcol;        // chunk 0
    const float* bq = bp + 32L * VOCAB;                   // chunk 1 onward

    if (tid == 0) s_cnt = 0;

    float rcur[8], rnext[8];

    // Prologue: chunk-0 loads; the id-filter runs in their shadow.
    #pragma unroll
    for (int p = 0; p < 8; p++)
        rcur[p] = __ldg(bp + (long)p * 4 * VOCAB);

    __syncthreads();   // s_cnt = 0 visible

    // Filter: find tokens whose id falls in this tile. Order irrelevant.
    const int4* __restrict__ ids4 = (const int4*)ids;
    for (int i = tid; i < N_TOK / 4; i += NTHREADS) {
        const int4 v = ids4[i];
        const int base_tok = i * 4;
        #pragma unroll
        for (int k = 0; k < 4; k++) {
            const int id = (&v.x)[k];
            if ((id >> TILE_BITS) == tile) {
                const int pos = atomicAdd(&s_cnt, 1);
                if (pos < CAP)
                    s_list[pos] = ((id & (TILE_C - 1)) << 16) | (base_tok + k);
            }
        }
    }
    __syncthreads();

    const int cnt = s_cnt;
    if (cnt == 0) return;                      // uniform block exit
    const bool overflow = (cnt > CAP);
    const int n = overflow ? 0 : cnt;

    for (int c = 0; c < N_CHUNK; c++) {
        // Issue chunk c+1 loads early (consumed next iteration).
        if (c + 1 < N_CHUNK) {
            #pragma unroll
            for (int p = 0; p < 8; p++)
                rnext[p] = __ldg(bq + (long)p * 4 * VOCAB);
            bq += 32L * VOCAB;
        }

        // Stage chunk c to smem. Safe: buf[c&1] last distributed in iter c-2;
        // every warp passed iter c-1's barrier before this STS.
        float* sstage = &buf[c & 1][0];
        #pragma unroll
        for (int p = 0; p < 8; p++)
            sstage[(p * 4 + lr) * PAD + lc] = rcur[p];
        __syncthreads();

        // Distribute chunk c: row = lane -> one coalesced 128B store/token.
        const int d0 = c * TILE_D;
        for (int s = wid; s < n; s += 16) {
            const int pk    = s_list[s];
            const int col   = pk >> 16;
            const int token = pk & 0xFFFF;
            out[(long)token * D_MODEL + d0 + lane] = sstage[lane * PAD + col];
        }
        if (overflow) {
            // Correct-for-any-input fallback (never taken here; idempotent).
            for (int s = wid; s < N_TOK; s += 16) {
                const int id = __ldg(&ids[s]);
                if ((id >> TILE_BITS) == tile)
                    out[(long)s * D_MODEL + d0 + lane] =
                        sstage[lane * PAD + (id & (TILE_C - 1))];
            }
        }

        #pragma unroll
        for (int p = 0; p < 8; p++) rcur[p] = rnext[p];
    }
}

extern "C" void kernel_launch(void* const* d_in, const int* in_sizes, int n_in,
                              void* d_out, int out_size) {
    const int* ids = nullptr;
    const float* W = nullptr;
    for (int i = 0; i < n_in; i++) {
        if (in_sizes[i] == N_TOK) ids = (const int*)d_in[i];
        else if (in_sizes[i] == D_MODEL * VOCAB) W = (const float*)d_in[i];
    }
    float* out = (float*)d_out;

    gather_tile_kernel<<<N_TILES, NTHREADS>>>(ids, W, out);
}